// round 13
// baseline (speedup 1.0000x reference)
#include <cuda_runtime.h>
#include <cstdint>
#include <math.h>

// ---------------------------------------------------------------------------
// Energy_Layer: all GEMMs bf16 mma.sync (m16n8k16); bf16 node intermediates.
// Scatter buffers are re-zeroed by their consumers (graph-replay invariant),
// eliminating the standalone zeroing pass.
//  scatter:  xs = segsum(x[src] -> dst), indeg, outdeg
//  node:     t  = tanh(xs@B^T + indeg*u + K0b);  h2 = relu(t@K1^T+K1b)
//            km = h2@M+bc;  out += (h2.v+c)*odeg
//  edge:     out += sum_e relu(tanh(q1[s]+q2[d])@U1^T + b1) . km[s]
// ---------------------------------------------------------------------------

#define N_NODES 50000
#define N_EDGES 500000
#define DIM     128
#define GRID_P  152

#define E_STRIDE 68      // uint32 words per 128-col bf16 row (proven)

// --- single-W bf16 smem (words): fusedK ---
#define G_B1  0
#define G_B2  128
#define G_RED 256
#define G_W   288
#define G_AS  (G_W + 128 * E_STRIDE)
#define SMEM_G ((G_AS + 128 * E_STRIDE) * 4)

// --- dual-W bf16 smem (words): k_dual / k_nodechain ---
#define N_B1  0
#define N_B2  128
#define N_V   256
#define N_RED 384
#define N_W1  416
#define N_W2  (N_W1 + 128 * E_STRIDE)
#define N_AS  (N_W2 + 128 * E_STRIDE)
#define SMEM_N ((N_AS + 128 * E_STRIDE) * 4)     // 106112 B

// --- edge smem (words, proven) ---
#define E_B2  0
#define E_RED 128
#define E_W   160
#define E_AS  (E_W + 128 * E_STRIDE)
#define SMEM_E ((E_AS + 128 * E_STRIDE) * 4)     // 70272 B

// device scratch (zero-initialized at load; kernels restore zeros after use)
__device__ uint32_t g_q1b[(size_t)N_NODES * 64];
__device__ uint32_t g_q2b[(size_t)N_NODES * 64];
__device__ uint32_t g_kmb[(size_t)N_NODES * 64];
__device__ uint32_t g_tb[(size_t)N_NODES * 64];
__device__ float g_agg[(size_t)N_NODES * DIM];
__device__ float g_deg[N_NODES];
__device__ float g_odeg[N_NODES];
__device__ float g_Mt[DIM * DIM];
__device__ float g_A1[DIM * DIM];
__device__ float g_A2[DIM * DIM];
__device__ float g_B[DIM * DIM];
__device__ float g_bc[DIM];
__device__ float g_v[DIM];
__device__ float g_c[1];
__device__ float g_bq1[DIM];
__device__ float g_u[DIM];
__device__ float g_zero[DIM];

// ---------------------------------------------------------------------------
__device__ __forceinline__ float tanha(float x) {
    float y;
    asm("tanh.approx.f32 %0, %1;" : "=f"(y) : "f"(x));
    return y;
}
__device__ __forceinline__ uint32_t packbf(float lo, float hi) {
    uint32_t r;
    asm("cvt.rn.bf16x2.f32 %0, %1, %2;" : "=r"(r) : "f"(hi), "f"(lo));
    return r;
}
__device__ __forceinline__ float bflo(uint32_t u) {
    return __uint_as_float(u << 16);
}
__device__ __forceinline__ float bfhi(uint32_t u) {
    return __uint_as_float(u & 0xffff0000u);
}
__device__ __forceinline__ void mma_bf16(float* c4, uint32_t a0, uint32_t a1,
                                         uint32_t a2, uint32_t a3,
                                         uint32_t b0, uint32_t b1) {
    asm volatile(
        "mma.sync.aligned.m16n8k16.row.col.f32.bf16.bf16.f32 "
        "{%0,%1,%2,%3},{%4,%5,%6,%7},{%8,%9},{%0,%1,%2,%3};"
        : "+f"(c4[0]), "+f"(c4[1]), "+f"(c4[2]), "+f"(c4[3])
        : "r"(a0), "r"(a1), "r"(a2), "r"(a3), "r"(b0), "r"(b1));
}

#define ZERO_ACC(acc)                                   \
    _Pragma("unroll") for (int _m = 0; _m < 2; _m++)    \
    _Pragma("unroll") for (int _n = 0; _n < 4; _n++)    \
    _Pragma("unroll") for (int _j = 0; _j < 4; _j++) acc[_m][_n][_j] = 0.f;

// bf16 inner GEMM (proven): warp tile 32x32, 8 kk steps of K=16
__device__ __forceinline__ void gemm_bf(const uint32_t* As, const uint32_t* Wb,
                                        float acc[2][4][4], int R0, int C0,
                                        int gr, int tg) {
#pragma unroll
    for (int kk = 0; kk < 8; kk++) {
        uint32_t a[2][4];
#pragma unroll
        for (int mt = 0; mt < 2; mt++) {
            const uint32_t* p = As + (R0 + mt * 16 + gr) * E_STRIDE + kk * 8 + tg;
            a[mt][0] = p[0];
            a[mt][1] = p[8 * E_STRIDE];
            a[mt][2] = p[4];
            a[mt][3] = p[8 * E_STRIDE + 4];
        }
#pragma unroll
        for (int nt = 0; nt < 4; nt++) {
            const uint32_t* q = Wb + (C0 + nt * 8 + gr) * E_STRIDE + kk * 8 + tg;
            uint32_t b0 = q[0];
            uint32_t b1 = q[4];
#pragma unroll
            for (int mt = 0; mt < 2; mt++)
                mma_bf16(acc[mt][nt], a[mt][0], a[mt][1], a[mt][2], a[mt][3],
                         b0, b1);
        }
    }
}

// W loader (fp32 row-major [n][k] -> bf16 packed)
__device__ __forceinline__ void load_W_bf(uint32_t* Wb,
                                          const float* __restrict__ W, int tid) {
#pragma unroll
    for (int i = 0; i < 8; i++) {
        int idx = i * 512 + tid;
        int n = idx >> 5, q = idx & 31;
        float4 w = *(const float4*)(W + n * DIM + q * 4);
        Wb[n * E_STRIDE + q * 2 + 0] = packbf(w.x, w.y);
        Wb[n * E_STRIDE + q * 2 + 1] = packbf(w.z, w.w);
    }
}

// A loader: fp32 source -> bf16 tile
__device__ __forceinline__ void load_A_f32(uint32_t* As,
                                           const float* __restrict__ A,
                                           int row0, int M, int tid) {
#pragma unroll
    for (int i = 0; i < 8; i++) {
        int idx = i * 512 + tid;
        int r = idx >> 5, q = idx & 31;
        int row = row0 + r;
        float4 v = make_float4(0.f, 0.f, 0.f, 0.f);
        if (row < M) v = *(const float4*)(A + (size_t)row * DIM + q * 4);
        As[r * E_STRIDE + q * 2 + 0] = packbf(v.x, v.y);
        As[r * E_STRIDE + q * 2 + 1] = packbf(v.z, v.w);
    }
}

// A loader: bf16 source -> bf16 tile (verbatim)
__device__ __forceinline__ void load_A_b16(uint32_t* As,
                                           const uint32_t* __restrict__ A,
                                           int row0, int M, int tid) {
#pragma unroll
    for (int i = 0; i < 4; i++) {
        int idx = i * 512 + tid;
        int r = idx >> 4, h = idx & 15;
        int row = row0 + r;
        uint4 v = make_uint4(0, 0, 0, 0);
        if (row < M) v = *(const uint4*)(A + (size_t)row * 64 + h * 4);
        *(uint4*)(As + r * E_STRIDE + h * 4) = v;
    }
}

// ---------------------------------------------------------------------------
// FUSED K-encoder (bf16): tb = bf16(tanh(xs@B^T + deg[r]*u + K0b))
// Re-zeros g_agg and g_deg after their single read (graph-replay invariant).
__global__ void __launch_bounds__(512, 1)
k_fusedK(float* __restrict__ XS, const float* __restrict__ B,
         const float* __restrict__ uu, const float* __restrict__ K0b,
         float* __restrict__ deg, uint32_t* __restrict__ tb, int M) {
    extern __shared__ uint32_t smu[];
    float* B1 = (float*)(smu + G_B1);
    float* B2 = (float*)(smu + G_B2);
    uint32_t* Wb = smu + G_W;
    uint32_t* As = smu + G_AS;
    const int tid = threadIdx.x;
    if (tid < 128) { B1[tid] = __ldg(K0b + tid); B2[tid] = __ldg(uu + tid); }
    load_W_bf(Wb, B, tid);
    __syncthreads();

    const int wid = tid >> 5, lane = tid & 31;
    const int gr = lane >> 2, tg = lane & 3;
    const int R0 = (wid >> 2) * 32, C0 = (wid & 3) * 32;
    const int tiles = (M + 127) >> 7;

    for (int tile = blockIdx.x; tile < tiles; tile += gridDim.x) {
        const int row0 = tile << 7;
        __syncthreads();
        // load agg tile (fp32 -> bf16), then zero the global copy in place
#pragma unroll
        for (int i = 0; i < 8; i++) {
            int idx = i * 512 + tid;
            int r = idx >> 5, q = idx & 31;
            int row = row0 + r;
            float4 v = make_float4(0.f, 0.f, 0.f, 0.f);
            if (row < M) {
                float4* p = (float4*)(XS + (size_t)row * DIM + q * 4);
                v = *p;
                *p = make_float4(0.f, 0.f, 0.f, 0.f);
            }
            As[r * E_STRIDE + q * 2 + 0] = packbf(v.x, v.y);
            As[r * E_STRIDE + q * 2 + 1] = packbf(v.z, v.w);
        }
        __syncthreads();
        float acc[2][4][4];
        ZERO_ACC(acc);
        gemm_bf(As, Wb, acc, R0, C0, gr, tg);
#pragma unroll
        for (int mt = 0; mt < 2; mt++) {
            int rl0 = R0 + mt * 16 + gr, rl1 = rl0 + 8;
            int g0 = row0 + rl0, g1 = row0 + rl1;
            float d0 = (g0 < M) ? __ldg(deg + g0) : 0.f;
            float d1 = (g1 < M) ? __ldg(deg + g1) : 0.f;
            if (C0 == 0 && tg == 0) {          // one thread per row zeroes deg
                if (g0 < M) deg[g0] = 0.f;
                if (g1 < M) deg[g1] = 0.f;
            }
#pragma unroll
            for (int nt = 0; nt < 4; nt++) {
                int c0 = C0 + nt * 8 + 2 * tg;
                float b0 = B1[c0], b1 = B1[c0 + 1];
                float u0 = B2[c0], u1 = B2[c0 + 1];
                if (g0 < M)
                    tb[(size_t)g0 * 64 + (c0 >> 1)] = packbf(
                        tanha(fmaf(d0, u0, acc[mt][nt][0] + b0)),
                        tanha(fmaf(d0, u1, acc[mt][nt][1] + b1)));
                if (g1 < M)
                    tb[(size_t)g1 * 64 + (c0 >> 1)] = packbf(
                        tanha(fmaf(d1, u0, acc[mt][nt][2] + b0)),
                        tanha(fmaf(d1, u1, acc[mt][nt][3] + b1)));
            }
        }
    }
}

// ---------------------------------------------------------------------------
// NODECHAIN (bf16): h2 = relu(t@K1^T+K1b); km = h2@M+bc;
//                   out += (h2.v+c)*odeg; re-zeros odeg after read.
__global__ void __launch_bounds__(512, 1)
k_nodechain(const uint32_t* __restrict__ Tb, const float* __restrict__ K1W,
            const float* __restrict__ K1b, const float* __restrict__ Mt,
            const float* __restrict__ bc, const float* __restrict__ vv,
            const float* __restrict__ cc, float* __restrict__ odeg,
            uint32_t* __restrict__ kmb, float* __restrict__ out, int M) {
    extern __shared__ uint32_t smu[];
    float* B1 = (float*)(smu + N_B1);
    float* B2 = (float*)(smu + N_B2);
    float* V = (float*)(smu + N_V);
    float* RED = (float*)(smu + N_RED);
    uint32_t* W1 = smu + N_W1;
    uint32_t* W2 = smu + N_W2;
    uint32_t* As = smu + N_AS;
    const int tid = threadIdx.x;
    if (tid < 128) { B1[tid] = __ldg(K1b + tid); B2[tid] = __ldg(bc + tid);
                     V[tid] = __ldg(vv + tid); }
    const float cval = __ldg(cc);
    load_W_bf(W1, K1W, tid);
    load_W_bf(W2, Mt, tid);
    __syncthreads();

    const int wid = tid >> 5, lane = tid & 31;
    const int gr = lane >> 2, tg = lane & 3;
    const int R0 = (wid >> 2) * 32, C0 = (wid & 3) * 32;
    const int tiles = (M + 127) >> 7;
    float part = 0.f;

    for (int tile = blockIdx.x; tile < tiles; tile += gridDim.x) {
        const int row0 = tile << 7;
        __syncthreads();
        load_A_b16(As, Tb, row0, M, tid);
        __syncthreads();
        float acc[2][4][4];
        ZERO_ACC(acc);
        gemm_bf(As, W1, acc, R0, C0, gr, tg);
        __syncthreads();
        // h2 = relu(acc + b1) -> As (bf16, in place)
#pragma unroll
        for (int mt = 0; mt < 2; mt++) {
            int rl0 = R0 + mt * 16 + gr, rl1 = rl0 + 8;
#pragma unroll
            for (int nt = 0; nt < 4; nt++) {
                int c0 = C0 + nt * 8 + 2 * tg;
                float b0 = B1[c0], b1 = B1[c0 + 1];
                As[rl0 * E_STRIDE + (c0 >> 1)] =
                    packbf(fmaxf(acc[mt][nt][0] + b0, 0.f),
                           fmaxf(acc[mt][nt][1] + b1, 0.f));
                As[rl1 * E_STRIDE + (c0 >> 1)] =
                    packbf(fmaxf(acc[mt][nt][2] + b0, 0.f),
                           fmaxf(acc[mt][nt][3] + b1, 0.f));
            }
        }
        __syncthreads();
        // kb = h2.v + c folded: part += kb * odeg[row]; zero odeg after read
        {
            int r = tid >> 2, qt = tid & 3;
            const uint32_t* hp = As + r * E_STRIDE + qt * 16;
            float s = 0.f;
#pragma unroll
            for (int j = 0; j < 16; j++) {
                uint32_t w = hp[j];
                s = fmaf(bflo(w), V[qt * 32 + 2 * j], s);
                s = fmaf(bfhi(w), V[qt * 32 + 2 * j + 1], s);
            }
            s += __shfl_xor_sync(0xffffffffu, s, 1);
            s += __shfl_xor_sync(0xffffffffu, s, 2);
            if (qt == 0 && row0 + r < M) {
                float od = odeg[row0 + r];
                odeg[row0 + r] = 0.f;
                part = fmaf(s + cval, od, part);
            }
        }
        // km = h2 @ M + bc
        ZERO_ACC(acc);
        gemm_bf(As, W2, acc, R0, C0, gr, tg);
#pragma unroll
        for (int mt = 0; mt < 2; mt++) {
            int rl0 = R0 + mt * 16 + gr, rl1 = rl0 + 8;
#pragma unroll
            for (int nt = 0; nt < 4; nt++) {
                int c0 = C0 + nt * 8 + 2 * tg;
                float b0 = B2[c0], b1 = B2[c0 + 1];
                if (row0 + rl0 < M)
                    kmb[(size_t)(row0 + rl0) * 64 + (c0 >> 1)] =
                        packbf(acc[mt][nt][0] + b0, acc[mt][nt][1] + b1);
                if (row0 + rl1 < M)
                    kmb[(size_t)(row0 + rl1) * 64 + (c0 >> 1)] =
                        packbf(acc[mt][nt][2] + b0, acc[mt][nt][3] + b1);
            }
        }
    }
#pragma unroll
    for (int o = 16; o > 0; o >>= 1)
        part += __shfl_xor_sync(0xffffffffu, part, o);
    __syncthreads();
    if (lane == 0) RED[wid] = part;
    __syncthreads();
    if (tid == 0) {
        float s = 0.f;
#pragma unroll
        for (int w = 0; w < 16; w++) s += RED[w];
        atomicAdd(out, s);
    }
}

// ---------------------------------------------------------------------------
// DUAL gemm (bf16): q1b = bf16(x@A1^T + bq1); q2b = bf16(x@A2^T)
__global__ void __launch_bounds__(512, 1)
k_dual(const float* __restrict__ A, const float* __restrict__ Wa,
       const float* __restrict__ ba, const float* __restrict__ Wb_,
       const float* __restrict__ bb, uint32_t* __restrict__ C1,
       uint32_t* __restrict__ C2, int M) {
    extern __shared__ uint32_t smu[];
    float* B1 = (float*)(smu + N_B1);
    float* B2 = (float*)(smu + N_B2);
    uint32_t* W1 = smu + N_W1;
    uint32_t* W2 = smu + N_W2;
    uint32_t* As = smu + N_AS;
    const int tid = threadIdx.x;
    if (tid < 128) { B1[tid] = __ldg(ba + tid); B2[tid] = __ldg(bb + tid); }
    load_W_bf(W1, Wa, tid);
    load_W_bf(W2, Wb_, tid);
    __syncthreads();

    const int wid = tid >> 5, lane = tid & 31;
    const int gr = lane >> 2, tg = lane & 3;
    const int R0 = (wid >> 2) * 32, C0 = (wid & 3) * 32;
    const int tiles = (M + 127) >> 7;

    for (int tile = blockIdx.x; tile < tiles; tile += gridDim.x) {
        const int row0 = tile << 7;
        __syncthreads();
        load_A_f32(As, A, row0, M, tid);
        __syncthreads();
#pragma unroll
        for (int pass = 0; pass < 2; pass++) {
            const uint32_t* Ws = pass ? W2 : W1;
            const float* Bs = pass ? B2 : B1;
            uint32_t* C = pass ? C2 : C1;
            float acc[2][4][4];
            ZERO_ACC(acc);
            gemm_bf(As, Ws, acc, R0, C0, gr, tg);
#pragma unroll
            for (int mt = 0; mt < 2; mt++) {
                int rl0 = R0 + mt * 16 + gr, rl1 = rl0 + 8;
#pragma unroll
                for (int nt = 0; nt < 4; nt++) {
                    int c0 = C0 + nt * 8 + 2 * tg;
                    float b0 = Bs[c0], b1 = Bs[c0 + 1];
                    if (row0 + rl0 < M)
                        C[(size_t)(row0 + rl0) * 64 + (c0 >> 1)] =
                            packbf(acc[mt][nt][0] + b0, acc[mt][nt][1] + b1);
                    if (row0 + rl1 < M)
                        C[(size_t)(row0 + rl1) * 64 + (c0 >> 1)] =
                            packbf(acc[mt][nt][2] + b0, acc[mt][nt][3] + b1);
                }
            }
        }
    }
}

// ---------------------------------------------------------------------------
// EDGE (bf16, proven): out += sum_e relu(tanh(q1[s]+q2[d])@U1^T + b1).km[s]
__global__ void __launch_bounds__(512, 1)
k_edge(const int* __restrict__ src, const int* __restrict__ dst,
       const uint32_t* __restrict__ Q1b, const uint32_t* __restrict__ Q2b,
       const float* __restrict__ U1W, const float* __restrict__ U1b,
       const uint32_t* __restrict__ kmb, float* __restrict__ out, int M) {
    extern __shared__ uint32_t smu[];
    float* B2 = (float*)(smu + E_B2);
    float* RED = (float*)(smu + E_RED);
    uint32_t* Wb = smu + E_W;
    uint32_t* As = smu + E_AS;
    const int tid = threadIdx.x;
    if (tid < 128) B2[tid] = __ldg(U1b + tid);
    load_W_bf(Wb, U1W, tid);
    __syncthreads();

    const int wid = tid >> 5, lane = tid & 31;
    const int gr = lane >> 2, tg = lane & 3;
    const int R0 = (wid >> 2) * 32, C0 = (wid & 3) * 32;
    const int tiles = (M + 127) >> 7;
    float part = 0.f;

    for (int tile = blockIdx.x; tile < tiles; tile += gridDim.x) {
        const int row0 = tile << 7;
        __syncthreads();
#pragma unroll
        for (int i = 0; i < 4; i++) {
            int idx = i * 512 + tid;
            int r = idx >> 4, h = idx & 15;
            int row = row0 + r;
            uint4 va = make_uint4(0, 0, 0, 0), vb = va;
            if (row < M) {
                int s = __ldg(src + row);
                int d = __ldg(dst + row);
                va = *(const uint4*)(Q1b + (size_t)s * 64 + h * 4);
                vb = *(const uint4*)(Q2b + (size_t)d * 64 + h * 4);
            }
            uint32_t o[4];
            uint32_t av[4] = {va.x, va.y, va.z, va.w};
            uint32_t bv[4] = {vb.x, vb.y, vb.z, vb.w};
#pragma unroll
            for (int j = 0; j < 4; j++) {
                float lo = tanha(bflo(av[j]) + bflo(bv[j]));
                float hi = tanha(bfhi(av[j]) + bfhi(bv[j]));
                o[j] = packbf(lo, hi);
            }
            *(uint4*)(As + r * E_STRIDE + h * 4) =
                make_uint4(o[0], o[1], o[2], o[3]);
        }
        __syncthreads();
        const uint32_t* kmp[4];
        bool kv[4];
#pragma unroll
        for (int j = 0; j < 4; j++) {
            int rg = row0 + R0 + ((j >> 1) * 16) + ((j & 1) * 8) + gr;
            kv[j] = rg < M;
            int s = kv[j] ? __ldg(src + rg) : 0;
            kmp[j] = kmb + (size_t)s * 64;
        }
        float acc[2][4][4];
        ZERO_ACC(acc);
        gemm_bf(As, Wb, acc, R0, C0, gr, tg);
#pragma unroll
        for (int mt = 0; mt < 2; mt++) {
            const uint32_t* km0 = kmp[mt * 2];
            const uint32_t* km1 = kmp[mt * 2 + 1];
            bool v0 = kv[mt * 2], v1 = kv[mt * 2 + 1];
#pragma unroll
            for (int nt = 0; nt < 4; nt++) {
                int c0 = C0 + nt * 8 + 2 * tg;
                float b0 = B2[c0], b1 = B2[c0 + 1];
                uint32_t kw0 = v0 ? km0[c0 >> 1] : 0u;
                uint32_t kw1 = v1 ? km1[c0 >> 1] : 0u;
                part = fmaf(fmaxf(acc[mt][nt][0] + b0, 0.f), bflo(kw0), part);
                part = fmaf(fmaxf(acc[mt][nt][1] + b1, 0.f), bfhi(kw0), part);
                part = fmaf(fmaxf(acc[mt][nt][2] + b0, 0.f), bflo(kw1), part);
                part = fmaf(fmaxf(acc[mt][nt][3] + b1, 0.f), bfhi(kw1), part);
            }
        }
    }
#pragma unroll
    for (int o = 16; o > 0; o >>= 1)
        part += __shfl_xor_sync(0xffffffffu, part, o);
    __syncthreads();
    if (lane == 0) RED[wid] = part;
    __syncthreads();
    if (tid == 0) {
        float s = 0.f;
#pragma unroll
        for (int w = 0; w < 16; w++) s += RED[w];
        atomicAdd(out, s);
    }
}

// ---------------------------------------------------------------------------
// scatter x rows + degree counts (buffers pre-zeroed by consumers/init)
__global__ void scatter_kernel(const float* __restrict__ x,
                               const int* __restrict__ src,
                               const int* __restrict__ dst) {
    int idx = blockIdx.x * blockDim.x + threadIdx.x;
    int e = idx >> 5;
    int q = (idx & 31) << 2;
    if (e < N_EDGES) {
        int s = __ldg(src + e);
        int d = __ldg(dst + e);
        float4 v = *(const float4*)(x + (size_t)s * DIM + q);
        atomicAdd((float4*)(g_agg + (size_t)d * DIM + q), v);
        if (q == 0) {
            atomicAdd(g_deg + d, 1.0f);
            atomicAdd(g_odeg + s, 1.0f);
        }
    }
}

// ---------------------------------------------------------------------------
// prep only (517 blocks): fused weights/biases + out[0] = 0
__global__ void k_prep(float* __restrict__ out,
                       const float* __restrict__ K2W,
                       const float* __restrict__ K2b,
                       const float* __restrict__ U2W,
                       const float* __restrict__ U2b,
                       const float* __restrict__ U0W,
                       const float* __restrict__ U0b,
                       const float* __restrict__ WencP1,
                       const float* __restrict__ bencP1,
                       const float* __restrict__ WencP2,
                       const float* __restrict__ bencP2,
                       const float* __restrict__ K0W,
                       const float* __restrict__ WencK,
                       const float* __restrict__ bencK) {
    __shared__ float sa[128];
    const int b = blockIdx.x, t = threadIdx.x;
    if (b == 0 && t == 0) out[0] = 0.0f;
    if (b < 128) {              // M[b][t] -> g_Mt[t][b] (transposed)
        sa[t] = K2W[t * DIM + b];
        __syncthreads();
        float s = 0.f;
        for (int k = 0; k < 128; k++) s = fmaf(sa[k], U2W[k * DIM + t], s);
        g_Mt[t * DIM + b] = s;
    } else if (b < 256) {
        int r = b - 128;
        sa[t] = U0W[r * DIM + t];
        __syncthreads();
        float s = 0.f;
        for (int k = 0; k < 128; k++) s = fmaf(sa[k], WencP1[k * DIM + t], s);
        g_A1[r * DIM + t] = s;
    } else if (b < 384) {
        int r = b - 256;
        sa[t] = U0W[r * DIM + t];
        __syncthreads();
        float s = 0.f;
        for (int k = 0; k < 128; k++) s = fmaf(sa[k], WencP2[k * DIM + t], s);
        g_A2[r * DIM + t] = s;
    } else if (b < 512) {
        int r = b - 384;
        sa[t] = K0W[r * DIM + t];
        __syncthreads();
        float s = 0.f;
        for (int k = 0; k < 128; k++) s = fmaf(sa[k], WencK[k * DIM + t], s);
        g_B[r * DIM + t] = s;
    } else if (b == 512) {
        sa[t] = K2b[t];
        __syncthreads();
        float s = 0.f;
        for (int k = 0; k < 128; k++) s = fmaf(sa[k], U2W[k * DIM + t], s);
        g_bc[t] = s;
    } else if (b == 513) {
        float s = 0.f;
        for (int k = 0; k < 128; k++) s = fmaf(K2W[k * DIM + t], U2b[k], s);
        g_v[t] = s;
        if (t == 0) {
            float cv = 0.f;
            for (int k = 0; k < 128; k++) cv = fmaf(K2b[k], U2b[k], cv);
            g_c[0] = cv;
        }
    } else if (b == 514) {
        sa[t] = __ldg(bencP1 + t) + __ldg(bencP2 + t);
        __syncthreads();
        float s = 0.f;
        for (int k = 0; k < 128; k++) s = fmaf(U0W[t * DIM + k], sa[k], s);
        g_bq1[t] = s + __ldg(U0b + t);
    } else {
        float s = 0.f;
        for (int k = 0; k < 128; k++)
            s = fmaf(K0W[t * DIM + k], __ldg(bencK + k), s);
        g_u[t] = s;
    }
}

// ---------------------------------------------------------------------------
extern "C" void kernel_launch(void* const* d_in, const int* in_sizes, int n_in,
                              void* d_out, int out_size) {
    const float* x      = (const float*)d_in[0];
    const int*   src    = (const int*)d_in[1];
    const int*   dst    = (const int*)d_in[2];
    const float* WencK  = (const float*)d_in[3];
    const float* bencK  = (const float*)d_in[4];
    const float* WencP1 = (const float*)d_in[5];
    const float* bencP1 = (const float*)d_in[6];
    const float* WencP2 = (const float*)d_in[7];
    const float* bencP2 = (const float*)d_in[8];
    const float* K0W = (const float*)d_in[9];
    const float* K0b = (const float*)d_in[10];
    const float* K1W = (const float*)d_in[11];
    const float* K1b = (const float*)d_in[12];
    const float* K2W = (const float*)d_in[13];
    const float* K2b = (const float*)d_in[14];
    const float* U0W = (const float*)d_in[15];
    const float* U0b = (const float*)d_in[16];
    const float* U1W = (const float*)d_in[17];
    const float* U1b = (const float*)d_in[18];
    const float* U2W = (const float*)d_in[19];
    const float* U2b = (const float*)d_in[20];
    float* out = (float*)d_out;

    float *agg, *deg, *odeg, *Mt, *A1, *A2, *Bw, *bc, *vv, *cc, *bq1, *uu, *zz;
    uint32_t *q1b, *q2b, *kmb, *tb;
    cudaGetSymbolAddress((void**)&q1b, g_q1b);
    cudaGetSymbolAddress((void**)&q2b, g_q2b);
    cudaGetSymbolAddress((void**)&kmb, g_kmb);
    cudaGetSymbolAddress((void**)&tb, g_tb);
    cudaGetSymbolAddress((void**)&agg, g_agg);
    cudaGetSymbolAddress((void**)&deg, g_deg);
    cudaGetSymbolAddress((void**)&odeg, g_odeg);
    cudaGetSymbolAddress((void**)&Mt, g_Mt);
    cudaGetSymbolAddress((void**)&A1, g_A1);
    cudaGetSymbolAddress((void**)&A2, g_A2);
    cudaGetSymbolAddress((void**)&Bw, g_B);
    cudaGetSymbolAddress((void**)&bc, g_bc);
    cudaGetSymbolAddress((void**)&vv, g_v);
    cudaGetSymbolAddress((void**)&cc, g_c);
    cudaGetSymbolAddress((void**)&bq1, g_bq1);
    cudaGetSymbolAddress((void**)&uu, g_u);
    cudaGetSymbolAddress((void**)&zz, g_zero);

    cudaFuncSetAttribute(k_fusedK, cudaFuncAttributeMaxDynamicSharedMemorySize, SMEM_G);
    cudaFuncSetAttribute(k_edge, cudaFuncAttributeMaxDynamicSharedMemorySize, SMEM_E);
    cudaFuncSetAttribute(k_dual, cudaFuncAttributeMaxDynamicSharedMemorySize, SMEM_N);
    cudaFuncSetAttribute(k_nodechain, cudaFuncAttributeMaxDynamicSharedMemorySize, SMEM_N);

    // prep fused weights + out[0]=0 (scatter buffers are already zero:
    // zero-initialized at load, re-zeroed by consumers every run)
    k_prep<<<517, 128>>>(out, K2W, K2b, U2W, U2b, U0W, U0b,
                         WencP1, bencP1, WencP2, bencP2, K0W, WencK, bencK);

    scatter_kernel<<<(N_EDGES * 32 + 255) / 256, 256>>>(x, src, dst);

    k_fusedK<<<GRID_P, 512, SMEM_G>>>(agg, Bw, uu, K0b, deg, tb, N_NODES);
    k_nodechain<<<GRID_P, 512, SMEM_N>>>(tb, K1W, K1b, Mt, bc, vv, cc,
                                         odeg, kmb, out, N_NODES);

    k_dual<<<GRID_P, 512, SMEM_N>>>(x, A1, bq1, A2, zz, q1b, q2b, N_NODES);

    k_edge<<<GRID_P, 512, SMEM_E>>>(src, dst, q1b, q2b, U1W, U1b, kmb, out,
                                    N_EDGES);
}

// round 14
// speedup vs baseline: 1.1644x; 1.1644x over previous
#include <cuda_runtime.h>
#include <cstdint>
#include <math.h>

// ---------------------------------------------------------------------------
// Energy_Layer: all GEMMs bf16 mma.sync (m16n8k16); bf16 node intermediates;
// segment-sum scatter via red.global.add.noftz.v4.bf16x2 (8 values/op).
//  scatter:  aggb = segsum(x[src] -> dst) in bf16, indeg, outdeg
//  node:     t  = tanh(agg@B^T + indeg*u + K0b);  h2 = relu(t@K1^T+K1b)
//            km = h2@M+bc;  out += (h2.v+c)*odeg
//  edge:     out += sum_e relu(tanh(q1[s]+q2[d])@U1^T + b1) . km[s]
// ---------------------------------------------------------------------------

#define N_NODES 50000
#define N_EDGES 500000
#define DIM     128
#define GRID_P  152

#define E_STRIDE 68      // uint32 words per 128-col bf16 row (proven)

// --- single-W bf16 smem (words): fusedK ---
#define G_B1  0
#define G_B2  128
#define G_RED 256
#define G_W   288
#define G_AS  (G_W + 128 * E_STRIDE)
#define SMEM_G ((G_AS + 128 * E_STRIDE) * 4)

// --- dual-W bf16 smem (words): k_dual / k_nodechain ---
#define N_B1  0
#define N_B2  128
#define N_V   256
#define N_RED 384
#define N_W1  416
#define N_W2  (N_W1 + 128 * E_STRIDE)
#define N_AS  (N_W2 + 128 * E_STRIDE)
#define SMEM_N ((N_AS + 128 * E_STRIDE) * 4)     // 106112 B

// --- edge smem (words, proven) ---
#define E_B2  0
#define E_RED 128
#define E_W   160
#define E_AS  (E_W + 128 * E_STRIDE)
#define SMEM_E ((E_AS + 128 * E_STRIDE) * 4)     // 70272 B

#define ZERO_BLKS 12500          // 12500*256 = 3.2e6 words = N_NODES*64

// device scratch
__device__ uint32_t g_q1b[(size_t)N_NODES * 64];
__device__ uint32_t g_q2b[(size_t)N_NODES * 64];
__device__ uint32_t g_kmb[(size_t)N_NODES * 64];
__device__ uint32_t g_tb[(size_t)N_NODES * 64];
__device__ uint32_t g_aggb[(size_t)N_NODES * 64];   // bf16x2 accumulators
__device__ float g_deg[N_NODES];
__device__ float g_odeg[N_NODES];
__device__ float g_Mt[DIM * DIM];
__device__ float g_A1[DIM * DIM];
__device__ float g_A2[DIM * DIM];
__device__ float g_B[DIM * DIM];
__device__ float g_bc[DIM];
__device__ float g_v[DIM];
__device__ float g_c[1];
__device__ float g_bq1[DIM];
__device__ float g_u[DIM];
__device__ float g_zero[DIM];

// ---------------------------------------------------------------------------
__device__ __forceinline__ float tanha(float x) {
    float y;
    asm("tanh.approx.f32 %0, %1;" : "=f"(y) : "f"(x));
    return y;
}
__device__ __forceinline__ uint32_t packbf(float lo, float hi) {
    uint32_t r;
    asm("cvt.rn.bf16x2.f32 %0, %1, %2;" : "=r"(r) : "f"(hi), "f"(lo));
    return r;
}
__device__ __forceinline__ float bflo(uint32_t u) {
    return __uint_as_float(u << 16);
}
__device__ __forceinline__ float bfhi(uint32_t u) {
    return __uint_as_float(u & 0xffff0000u);
}
__device__ __forceinline__ void mma_bf16(float* c4, uint32_t a0, uint32_t a1,
                                         uint32_t a2, uint32_t a3,
                                         uint32_t b0, uint32_t b1) {
    asm volatile(
        "mma.sync.aligned.m16n8k16.row.col.f32.bf16.bf16.f32 "
        "{%0,%1,%2,%3},{%4,%5,%6,%7},{%8,%9},{%0,%1,%2,%3};"
        : "+f"(c4[0]), "+f"(c4[1]), "+f"(c4[2]), "+f"(c4[3])
        : "r"(a0), "r"(a1), "r"(a2), "r"(a3), "r"(b0), "r"(b1));
}
__device__ __forceinline__ void red_bf16x8(uint32_t* ptr, uint32_t a,
                                           uint32_t b, uint32_t c, uint32_t d) {
    asm volatile(
        "red.global.add.noftz.v4.bf16x2 [%0], {%1, %2, %3, %4};"
        :: "l"(ptr), "r"(a), "r"(b), "r"(c), "r"(d) : "memory");
}

#define ZERO_ACC(acc)                                   \
    _Pragma("unroll") for (int _m = 0; _m < 2; _m++)    \
    _Pragma("unroll") for (int _n = 0; _n < 4; _n++)    \
    _Pragma("unroll") for (int _j = 0; _j < 4; _j++) acc[_m][_n][_j] = 0.f;

// bf16 inner GEMM (proven): warp tile 32x32, 8 kk steps of K=16
__device__ __forceinline__ void gemm_bf(const uint32_t* As, const uint32_t* Wb,
                                        float acc[2][4][4], int R0, int C0,
                                        int gr, int tg) {
#pragma unroll
    for (int kk = 0; kk < 8; kk++) {
        uint32_t a[2][4];
#pragma unroll
        for (int mt = 0; mt < 2; mt++) {
            const uint32_t* p = As + (R0 + mt * 16 + gr) * E_STRIDE + kk * 8 + tg;
            a[mt][0] = p[0];
            a[mt][1] = p[8 * E_STRIDE];
            a[mt][2] = p[4];
            a[mt][3] = p[8 * E_STRIDE + 4];
        }
#pragma unroll
        for (int nt = 0; nt < 4; nt++) {
            const uint32_t* q = Wb + (C0 + nt * 8 + gr) * E_STRIDE + kk * 8 + tg;
            uint32_t b0 = q[0];
            uint32_t b1 = q[4];
#pragma unroll
            for (int mt = 0; mt < 2; mt++)
                mma_bf16(acc[mt][nt], a[mt][0], a[mt][1], a[mt][2], a[mt][3],
                         b0, b1);
        }
    }
}

// W loader (fp32 row-major [n][k] -> bf16 packed)
__device__ __forceinline__ void load_W_bf(uint32_t* Wb,
                                          const float* __restrict__ W, int tid) {
#pragma unroll
    for (int i = 0; i < 8; i++) {
        int idx = i * 512 + tid;
        int n = idx >> 5, q = idx & 31;
        float4 w = *(const float4*)(W + n * DIM + q * 4);
        Wb[n * E_STRIDE + q * 2 + 0] = packbf(w.x, w.y);
        Wb[n * E_STRIDE + q * 2 + 1] = packbf(w.z, w.w);
    }
}

// A loader: fp32 source -> bf16 tile
__device__ __forceinline__ void load_A_f32(uint32_t* As,
                                           const float* __restrict__ A,
                                           int row0, int M, int tid) {
#pragma unroll
    for (int i = 0; i < 8; i++) {
        int idx = i * 512 + tid;
        int r = idx >> 5, q = idx & 31;
        int row = row0 + r;
        float4 v = make_float4(0.f, 0.f, 0.f, 0.f);
        if (row < M) v = *(const float4*)(A + (size_t)row * DIM + q * 4);
        As[r * E_STRIDE + q * 2 + 0] = packbf(v.x, v.y);
        As[r * E_STRIDE + q * 2 + 1] = packbf(v.z, v.w);
    }
}

// A loader: bf16 source -> bf16 tile (verbatim)
__device__ __forceinline__ void load_A_b16(uint32_t* As,
                                           const uint32_t* __restrict__ A,
                                           int row0, int M, int tid) {
#pragma unroll
    for (int i = 0; i < 4; i++) {
        int idx = i * 512 + tid;
        int r = idx >> 4, h = idx & 15;
        int row = row0 + r;
        uint4 v = make_uint4(0, 0, 0, 0);
        if (row < M) v = *(const uint4*)(A + (size_t)row * 64 + h * 4);
        *(uint4*)(As + r * E_STRIDE + h * 4) = v;
    }
}

// ---------------------------------------------------------------------------
// FUSED K-encoder (bf16): tb = bf16(tanh(aggb@B^T + deg[r]*u + K0b))
__global__ void __launch_bounds__(512, 1)
k_fusedK(const uint32_t* __restrict__ XSb, const float* __restrict__ B,
         const float* __restrict__ uu, const float* __restrict__ K0b,
         const float* __restrict__ deg, uint32_t* __restrict__ tb, int M) {
    extern __shared__ uint32_t smu[];
    float* B1 = (float*)(smu + G_B1);
    float* B2 = (float*)(smu + G_B2);
    uint32_t* Wb = smu + G_W;
    uint32_t* As = smu + G_AS;
    const int tid = threadIdx.x;
    if (tid < 128) { B1[tid] = __ldg(K0b + tid); B2[tid] = __ldg(uu + tid); }
    load_W_bf(Wb, B, tid);
    __syncthreads();

    const int wid = tid >> 5, lane = tid & 31;
    const int gr = lane >> 2, tg = lane & 3;
    const int R0 = (wid >> 2) * 32, C0 = (wid & 3) * 32;
    const int tiles = (M + 127) >> 7;

    for (int tile = blockIdx.x; tile < tiles; tile += gridDim.x) {
        const int row0 = tile << 7;
        __syncthreads();
        load_A_b16(As, XSb, row0, M, tid);
        __syncthreads();
        float acc[2][4][4];
        ZERO_ACC(acc);
        gemm_bf(As, Wb, acc, R0, C0, gr, tg);
#pragma unroll
        for (int mt = 0; mt < 2; mt++) {
            int rl0 = R0 + mt * 16 + gr, rl1 = rl0 + 8;
            int g0 = row0 + rl0, g1 = row0 + rl1;
            float d0 = (g0 < M) ? __ldg(deg + g0) : 0.f;
            float d1 = (g1 < M) ? __ldg(deg + g1) : 0.f;
#pragma unroll
            for (int nt = 0; nt < 4; nt++) {
                int c0 = C0 + nt * 8 + 2 * tg;
                float b0 = B1[c0], b1 = B1[c0 + 1];
                float u0 = B2[c0], u1 = B2[c0 + 1];
                if (g0 < M)
                    tb[(size_t)g0 * 64 + (c0 >> 1)] = packbf(
                        tanhf(fmaf(d0, u0, acc[mt][nt][0] + b0)),
                        tanhf(fmaf(d0, u1, acc[mt][nt][1] + b1)));
                if (g1 < M)
                    tb[(size_t)g1 * 64 + (c0 >> 1)] = packbf(
                        tanhf(fmaf(d1, u0, acc[mt][nt][2] + b0)),
                        tanhf(fmaf(d1, u1, acc[mt][nt][3] + b1)));
            }
        }
    }
}

// ---------------------------------------------------------------------------
// NODECHAIN (bf16): h2 = relu(t@K1^T+K1b); km = h2@M+bc;
//                   out += (h2.v+c)*odeg (folded)
__global__ void __launch_bounds__(512, 1)
k_nodechain(const uint32_t* __restrict__ Tb, const float* __restrict__ K1W,
            const float* __restrict__ K1b, const float* __restrict__ Mt,
            const float* __restrict__ bc, const float* __restrict__ vv,
            const float* __restrict__ cc, const float* __restrict__ odeg,
            uint32_t* __restrict__ kmb, float* __restrict__ out, int M) {
    extern __shared__ uint32_t smu[];
    float* B1 = (float*)(smu + N_B1);
    float* B2 = (float*)(smu + N_B2);
    float* V = (float*)(smu + N_V);
    float* RED = (float*)(smu + N_RED);
    uint32_t* W1 = smu + N_W1;
    uint32_t* W2 = smu + N_W2;
    uint32_t* As = smu + N_AS;
    const int tid = threadIdx.x;
    if (tid < 128) { B1[tid] = __ldg(K1b + tid); B2[tid] = __ldg(bc + tid);
                     V[tid] = __ldg(vv + tid); }
    const float cval = __ldg(cc);
    load_W_bf(W1, K1W, tid);
    load_W_bf(W2, Mt, tid);
    __syncthreads();

    const int wid = tid >> 5, lane = tid & 31;
    const int gr = lane >> 2, tg = lane & 3;
    const int R0 = (wid >> 2) * 32, C0 = (wid & 3) * 32;
    const int tiles = (M + 127) >> 7;
    float part = 0.f;

    for (int tile = blockIdx.x; tile < tiles; tile += gridDim.x) {
        const int row0 = tile << 7;
        __syncthreads();
        load_A_b16(As, Tb, row0, M, tid);
        __syncthreads();
        float acc[2][4][4];
        ZERO_ACC(acc);
        gemm_bf(As, W1, acc, R0, C0, gr, tg);
        __syncthreads();
        // h2 = relu(acc + b1) -> As (bf16, in place)
#pragma unroll
        for (int mt = 0; mt < 2; mt++) {
            int rl0 = R0 + mt * 16 + gr, rl1 = rl0 + 8;
#pragma unroll
            for (int nt = 0; nt < 4; nt++) {
                int c0 = C0 + nt * 8 + 2 * tg;
                float b0 = B1[c0], b1 = B1[c0 + 1];
                As[rl0 * E_STRIDE + (c0 >> 1)] =
                    packbf(fmaxf(acc[mt][nt][0] + b0, 0.f),
                           fmaxf(acc[mt][nt][1] + b1, 0.f));
                As[rl1 * E_STRIDE + (c0 >> 1)] =
                    packbf(fmaxf(acc[mt][nt][2] + b0, 0.f),
                           fmaxf(acc[mt][nt][3] + b1, 0.f));
            }
        }
        __syncthreads();
        // kb = h2.v + c folded: part += kb * odeg[row]
        {
            int r = tid >> 2, qt = tid & 3;
            const uint32_t* hp = As + r * E_STRIDE + qt * 16;
            float s = 0.f;
#pragma unroll
            for (int j = 0; j < 16; j++) {
                uint32_t w = hp[j];
                s = fmaf(bflo(w), V[qt * 32 + 2 * j], s);
                s = fmaf(bfhi(w), V[qt * 32 + 2 * j + 1], s);
            }
            s += __shfl_xor_sync(0xffffffffu, s, 1);
            s += __shfl_xor_sync(0xffffffffu, s, 2);
            if (qt == 0 && row0 + r < M)
                part = fmaf(s + cval, __ldg(odeg + row0 + r), part);
        }
        // km = h2 @ M + bc
        ZERO_ACC(acc);
        gemm_bf(As, W2, acc, R0, C0, gr, tg);
#pragma unroll
        for (int mt = 0; mt < 2; mt++) {
            int rl0 = R0 + mt * 16 + gr, rl1 = rl0 + 8;
#pragma unroll
            for (int nt = 0; nt < 4; nt++) {
                int c0 = C0 + nt * 8 + 2 * tg;
                float b0 = B2[c0], b1 = B2[c0 + 1];
                if (row0 + rl0 < M)
                    kmb[(size_t)(row0 + rl0) * 64 + (c0 >> 1)] =
                        packbf(acc[mt][nt][0] + b0, acc[mt][nt][1] + b1);
                if (row0 + rl1 < M)
                    kmb[(size_t)(row0 + rl1) * 64 + (c0 >> 1)] =
                        packbf(acc[mt][nt][2] + b0, acc[mt][nt][3] + b1);
            }
        }
    }
#pragma unroll
    for (int o = 16; o > 0; o >>= 1)
        part += __shfl_xor_sync(0xffffffffu, part, o);
    __syncthreads();
    if (lane == 0) RED[wid] = part;
    __syncthreads();
    if (tid == 0) {
        float s = 0.f;
#pragma unroll
        for (int w = 0; w < 16; w++) s += RED[w];
        atomicAdd(out, s);
    }
}

// ---------------------------------------------------------------------------
// DUAL gemm (bf16): q1b = bf16(x@A1^T + bq1); q2b = bf16(x@A2^T)
__global__ void __launch_bounds__(512, 1)
k_dual(const float* __restrict__ A, const float* __restrict__ Wa,
       const float* __restrict__ ba, const float* __restrict__ Wb_,
       const float* __restrict__ bb, uint32_t* __restrict__ C1,
       uint32_t* __restrict__ C2, int M) {
    extern __shared__ uint32_t smu[];
    float* B1 = (float*)(smu + N_B1);
    float* B2 = (float*)(smu + N_B2);
    uint32_t* W1 = smu + N_W1;
    uint32_t* W2 = smu + N_W2;
    uint32_t* As = smu + N_AS;
    const int tid = threadIdx.x;
    if (tid < 128) { B1[tid] = __ldg(ba + tid); B2[tid] = __ldg(bb + tid); }
    load_W_bf(W1, Wa, tid);
    load_W_bf(W2, Wb_, tid);
    __syncthreads();

    const int wid = tid >> 5, lane = tid & 31;
    const int gr = lane >> 2, tg = lane & 3;
    const int R0 = (wid >> 2) * 32, C0 = (wid & 3) * 32;
    const int tiles = (M + 127) >> 7;

    for (int tile = blockIdx.x; tile < tiles; tile += gridDim.x) {
        const int row0 = tile << 7;
        __syncthreads();
        load_A_f32(As, A, row0, M, tid);
        __syncthreads();
#pragma unroll
        for (int pass = 0; pass < 2; pass++) {
            const uint32_t* Ws = pass ? W2 : W1;
            const float* Bs = pass ? B2 : B1;
            uint32_t* C = pass ? C2 : C1;
            float acc[2][4][4];
            ZERO_ACC(acc);
            gemm_bf(As, Ws, acc, R0, C0, gr, tg);
#pragma unroll
            for (int mt = 0; mt < 2; mt++) {
                int rl0 = R0 + mt * 16 + gr, rl1 = rl0 + 8;
#pragma unroll
                for (int nt = 0; nt < 4; nt++) {
                    int c0 = C0 + nt * 8 + 2 * tg;
                    float b0 = Bs[c0], b1 = Bs[c0 + 1];
                    if (row0 + rl0 < M)
                        C[(size_t)(row0 + rl0) * 64 + (c0 >> 1)] =
                            packbf(acc[mt][nt][0] + b0, acc[mt][nt][1] + b1);
                    if (row0 + rl1 < M)
                        C[(size_t)(row0 + rl1) * 64 + (c0 >> 1)] =
                            packbf(acc[mt][nt][2] + b0, acc[mt][nt][3] + b1);
                }
            }
        }
    }
}

// ---------------------------------------------------------------------------
// EDGE (bf16, proven): out += sum_e relu(tanh(q1[s]+q2[d])@U1^T + b1).km[s]
__global__ void __launch_bounds__(512, 1)
k_edge(const int* __restrict__ src, const int* __restrict__ dst,
       const uint32_t* __restrict__ Q1b, const uint32_t* __restrict__ Q2b,
       const float* __restrict__ U1W, const float* __restrict__ U1b,
       const uint32_t* __restrict__ kmb, float* __restrict__ out, int M) {
    extern __shared__ uint32_t smu[];
    float* B2 = (float*)(smu + E_B2);
    float* RED = (float*)(smu + E_RED);
    uint32_t* Wb = smu + E_W;
    uint32_t* As = smu + E_AS;
    const int tid = threadIdx.x;
    if (tid < 128) B2[tid] = __ldg(U1b + tid);
    load_W_bf(Wb, U1W, tid);
    __syncthreads();

    const int wid = tid >> 5, lane = tid & 31;
    const int gr = lane >> 2, tg = lane & 3;
    const int R0 = (wid >> 2) * 32, C0 = (wid & 3) * 32;
    const int tiles = (M + 127) >> 7;
    float part = 0.f;

    for (int tile = blockIdx.x; tile < tiles; tile += gridDim.x) {
        const int row0 = tile << 7;
        __syncthreads();
#pragma unroll
        for (int i = 0; i < 4; i++) {
            int idx = i * 512 + tid;
            int r = idx >> 4, h = idx & 15;
            int row = row0 + r;
            uint4 va = make_uint4(0, 0, 0, 0), vb = va;
            if (row < M) {
                int s = __ldg(src + row);
                int d = __ldg(dst + row);
                va = *(const uint4*)(Q1b + (size_t)s * 64 + h * 4);
                vb = *(const uint4*)(Q2b + (size_t)d * 64 + h * 4);
            }
            uint32_t o[4];
            uint32_t av[4] = {va.x, va.y, va.z, va.w};
            uint32_t bv[4] = {vb.x, vb.y, vb.z, vb.w};
#pragma unroll
            for (int j = 0; j < 4; j++) {
                float lo = tanha(bflo(av[j]) + bflo(bv[j]));
                float hi = tanha(bfhi(av[j]) + bfhi(bv[j]));
                o[j] = packbf(lo, hi);
            }
            *(uint4*)(As + r * E_STRIDE + h * 4) =
                make_uint4(o[0], o[1], o[2], o[3]);
        }
        __syncthreads();
        const uint32_t* kmp[4];
        bool kv[4];
#pragma unroll
        for (int j = 0; j < 4; j++) {
            int rg = row0 + R0 + ((j >> 1) * 16) + ((j & 1) * 8) + gr;
            kv[j] = rg < M;
            int s = kv[j] ? __ldg(src + rg) : 0;
            kmp[j] = kmb + (size_t)s * 64;
        }
        float acc[2][4][4];
        ZERO_ACC(acc);
        gemm_bf(As, Wb, acc, R0, C0, gr, tg);
#pragma unroll
        for (int mt = 0; mt < 2; mt++) {
            const uint32_t* km0 = kmp[mt * 2];
            const uint32_t* km1 = kmp[mt * 2 + 1];
            bool v0 = kv[mt * 2], v1 = kv[mt * 2 + 1];
#pragma unroll
            for (int nt = 0; nt < 4; nt++) {
                int c0 = C0 + nt * 8 + 2 * tg;
                float b0 = B2[c0], b1 = B2[c0 + 1];
                uint32_t kw0 = v0 ? km0[c0 >> 1] : 0u;
                uint32_t kw1 = v1 ? km1[c0 >> 1] : 0u;
                part = fmaf(fmaxf(acc[mt][nt][0] + b0, 0.f), bflo(kw0), part);
                part = fmaf(fmaxf(acc[mt][nt][1] + b1, 0.f), bfhi(kw0), part);
                part = fmaf(fmaxf(acc[mt][nt][2] + b0, 0.f), bflo(kw1), part);
                part = fmaf(fmaxf(acc[mt][nt][3] + b1, 0.f), bfhi(kw1), part);
            }
        }
    }
#pragma unroll
    for (int o = 16; o > 0; o >>= 1)
        part += __shfl_xor_sync(0xffffffffu, part, o);
    __syncthreads();
    if (lane == 0) RED[wid] = part;
    __syncthreads();
    if (tid == 0) {
        float s = 0.f;
#pragma unroll
        for (int w = 0; w < 16; w++) s += RED[w];
        atomicAdd(out, s);
    }
}

// ---------------------------------------------------------------------------
// scatter: aggb[dst[e]] += bf16(x[src[e]]) via v4.bf16x2 reds; 16 thr/edge
__global__ void scatter_kernel(const float* __restrict__ x,
                               const int* __restrict__ src,
                               const int* __restrict__ dst) {
    int idx = blockIdx.x * blockDim.x + threadIdx.x;
    int e = idx >> 4;
    int h = idx & 15;            // 8 floats per thread
    if (e < N_EDGES) {
        int s = __ldg(src + e);
        int d = __ldg(dst + e);
        const float* xp = x + (size_t)s * DIM + h * 8;
        float4 v0 = *(const float4*)(xp);
        float4 v1 = *(const float4*)(xp + 4);
        red_bf16x8(g_aggb + (size_t)d * 64 + h * 4,
                   packbf(v0.x, v0.y), packbf(v0.z, v0.w),
                   packbf(v1.x, v1.y), packbf(v1.z, v1.w));
        if (h == 0) {
            atomicAdd(g_deg + d, 1.0f);
            atomicAdd(g_odeg + s, 1.0f);
        }
    }
}

// ---------------------------------------------------------------------------
// FUSED zero + prep (role by blockIdx); g_Mt stored TRANSPOSED
__global__ void k_zero_prep(float* __restrict__ out,
                            const float* __restrict__ K2W,
                            const float* __restrict__ K2b,
                            const float* __restrict__ U2W,
                            const float* __restrict__ U2b,
                            const float* __restrict__ U0W,
                            const float* __restrict__ U0b,
                            const float* __restrict__ WencP1,
                            const float* __restrict__ bencP1,
                            const float* __restrict__ WencP2,
                            const float* __restrict__ bencP2,
                            const float* __restrict__ K0W,
                            const float* __restrict__ WencK,
                            const float* __restrict__ bencK) {
    __shared__ float sa[128];
    const int tid = threadIdx.x;
    if (blockIdx.x < ZERO_BLKS) {
        int i = blockIdx.x * 256 + tid;
        if (i < N_NODES * 64) g_aggb[i] = 0u;
        if (i < N_NODES) { g_deg[i] = 0.0f; g_odeg[i] = 0.0f; }
        if (i == 0) out[0] = 0.0f;
        return;
    }
    const int b = blockIdx.x - ZERO_BLKS;
    const int t = tid;
    const bool a = t < 128;
    if (b < 128) {              // M[b][t] -> g_Mt[t][b] (transposed)
        if (a) sa[t] = K2W[t * DIM + b];
        __syncthreads();
        if (a) {
            float s = 0.f;
            for (int k = 0; k < 128; k++) s = fmaf(sa[k], U2W[k * DIM + t], s);
            g_Mt[t * DIM + b] = s;
        }
    } else if (b < 256) {
        int r = b - 128;
        if (a) sa[t] = U0W[r * DIM + t];
        __syncthreads();
        if (a) {
            float s = 0.f;
            for (int k = 0; k < 128; k++) s = fmaf(sa[k], WencP1[k * DIM + t], s);
            g_A1[r * DIM + t] = s;
        }
    } else if (b < 384) {
        int r = b - 256;
        if (a) sa[t] = U0W[r * DIM + t];
        __syncthreads();
        if (a) {
            float s = 0.f;
            for (int k = 0; k < 128; k++) s = fmaf(sa[k], WencP2[k * DIM + t], s);
            g_A2[r * DIM + t] = s;
        }
    } else if (b < 512) {
        int r = b - 384;
        if (a) sa[t] = K0W[r * DIM + t];
        __syncthreads();
        if (a) {
            float s = 0.f;
            for (int k = 0; k < 128; k++) s = fmaf(sa[k], WencK[k * DIM + t], s);
            g_B[r * DIM + t] = s;
        }
    } else if (b == 512) {
        if (a) sa[t] = K2b[t];
        __syncthreads();
        if (a) {
            float s = 0.f;
            for (int k = 0; k < 128; k++) s = fmaf(sa[k], U2W[k * DIM + t], s);
            g_bc[t] = s;
        }
    } else if (b == 513) {
        if (a) {
            float s = 0.f;
            for (int k = 0; k < 128; k++) s = fmaf(K2W[k * DIM + t], U2b[k], s);
            g_v[t] = s;
            if (t == 0) {
                float cv = 0.f;
                for (int k = 0; k < 128; k++) cv = fmaf(K2b[k], U2b[k], cv);
                g_c[0] = cv;
            }
        }
    } else if (b == 514) {
        if (a) sa[t] = __ldg(bencP1 + t) + __ldg(bencP2 + t);
        __syncthreads();
        if (a) {
            float s = 0.f;
            for (int k = 0; k < 128; k++) s = fmaf(U0W[t * DIM + k], sa[k], s);
            g_bq1[t] = s + __ldg(U0b + t);
        }
    } else {
        if (a) {
            float s = 0.f;
            for (int k = 0; k < 128; k++)
                s = fmaf(K0W[t * DIM + k], __ldg(bencK + k), s);
            g_u[t] = s;
        }
    }
}

// ---------------------------------------------------------------------------
extern "C" void kernel_launch(void* const* d_in, const int* in_sizes, int n_in,
                              void* d_out, int out_size) {
    const float* x      = (const float*)d_in[0];
    const int*   src    = (const int*)d_in[1];
    const int*   dst    = (const int*)d_in[2];
    const float* WencK  = (const float*)d_in[3];
    const float* bencK  = (const float*)d_in[4];
    const float* WencP1 = (const float*)d_in[5];
    const float* bencP1 = (const float*)d_in[6];
    const float* WencP2 = (const float*)d_in[7];
    const float* bencP2 = (const float*)d_in[8];
    const float* K0W = (const float*)d_in[9];
    const float* K0b = (const float*)d_in[10];
    const float* K1W = (const float*)d_in[11];
    const float* K1b = (const float*)d_in[12];
    const float* K2W = (const float*)d_in[13];
    const float* K2b = (const float*)d_in[14];
    const float* U0W = (const float*)d_in[15];
    const float* U0b = (const float*)d_in[16];
    const float* U1W = (const float*)d_in[17];
    const float* U1b = (const float*)d_in[18];
    const float* U2W = (const float*)d_in[19];
    const float* U2b = (const float*)d_in[20];
    float* out = (float*)d_out;

    float *deg, *odeg, *Mt, *A1, *A2, *Bw, *bc, *vv, *cc, *bq1, *uu, *zz;
    uint32_t *q1b, *q2b, *kmb, *tb, *aggb;
    cudaGetSymbolAddress((void**)&q1b, g_q1b);
    cudaGetSymbolAddress((void**)&q2b, g_q2b);
    cudaGetSymbolAddress((void**)&kmb, g_kmb);
    cudaGetSymbolAddress((void**)&tb, g_tb);
    cudaGetSymbolAddress((void**)&aggb, g_aggb);
    cudaGetSymbolAddress((void**)&deg, g_deg);
    cudaGetSymbolAddress((void**)&odeg, g_odeg);
    cudaGetSymbolAddress((void**)&Mt, g_Mt);
    cudaGetSymbolAddress((void**)&A1, g_A1);
    cudaGetSymbolAddress((void**)&A2, g_A2);
    cudaGetSymbolAddress((void**)&Bw, g_B);
    cudaGetSymbolAddress((void**)&bc, g_bc);
    cudaGetSymbolAddress((void**)&vv, g_v);
    cudaGetSymbolAddress((void**)&cc, g_c);
    cudaGetSymbolAddress((void**)&bq1, g_bq1);
    cudaGetSymbolAddress((void**)&uu, g_u);
    cudaGetSymbolAddress((void**)&zz, g_zero);

    cudaFuncSetAttribute(k_fusedK, cudaFuncAttributeMaxDynamicSharedMemorySize, SMEM_G);
    cudaFuncSetAttribute(k_edge, cudaFuncAttributeMaxDynamicSharedMemorySize, SMEM_E);
    cudaFuncSetAttribute(k_dual, cudaFuncAttributeMaxDynamicSharedMemorySize, SMEM_N);
    cudaFuncSetAttribute(k_nodechain, cudaFuncAttributeMaxDynamicSharedMemorySize, SMEM_N);

    k_zero_prep<<<ZERO_BLKS + 516, 256>>>(out, K2W, K2b, U2W, U2b, U0W, U0b,
                                          WencP1, bencP1, WencP2, bencP2,
                                          K0W, WencK, bencK);

    scatter_kernel<<<(N_EDGES * 16 + 255) / 256, 256>>>(x, src, dst);

    k_fusedK<<<GRID_P, 512, SMEM_G>>>(aggb, Bw, uu, K0b, deg, tb, N_NODES);
    k_nodechain<<<GRID_P, 512, SMEM_N>>>(tb, K1W, K1b, Mt, bc, vv, cc,
                                         odeg, kmb, out, N_NODES);

    k_dual<<<GRID_P, 512, SMEM_N>>>(x, A1, bq1, A2, zz, q1b, q2b, N_NODES);

    k_edge<<<GRID_P, 512, SMEM_E>>>(src, dst, q1b, q2b, U1W, U1b, kmb, out,
                                    N_EDGES);
}

// round 15
// speedup vs baseline: 1.2391x; 1.0642x over previous
#include <cuda_runtime.h>
#include <cstdint>
#include <math.h>

// ---------------------------------------------------------------------------
// Energy_Layer: all GEMMs bf16 mma.sync (m16n8k16); bf16 intermediates;
// bf16 v4 atomic scatter; single mega-fused node kernel (5 GEMMs, t in smem).
//  scatter:  aggb = segsum(x[src] -> dst) bf16, indeg, outdeg
//  node:     q1 = x@A1^T+bq1; q2 = x@A2^T;  t = tanh(aggb@B^T + deg*u + K0b)
//            h2 = relu(t@K1^T+K1b); km = h2@M+bc; out += (h2.v+c)*odeg
//  edge:     out += sum_e relu(tanh(q1[s]+q2[d])@U1^T + b1) . km[s]
// ---------------------------------------------------------------------------

#define N_NODES 50000
#define N_EDGES 500000
#define DIM     128
#define GRID_P  152

#define E_STRIDE 68      // uint32 words per 128-col bf16 row (proven)
#define WT (128 * E_STRIDE)   // one 128x128 bf16 tile in words (8704)

// --- node mega-kernel smem (words): 5 W tiles + 1 work tile ---
#define M_BQ1 0
#define M_K0B 128
#define M_U   256
#define M_K1B 384
#define M_BC  512
#define M_V   640
#define M_RED 768
#define M_W0  800               // A1, A2, B, K1, Mt consecutively
#define M_AS  (M_W0 + 5 * WT)
#define SMEM_M ((M_AS + WT) * 4)        // 212096 B

// --- edge smem (words, proven) ---
#define E_B2  0
#define E_RED 128
#define E_W   160
#define E_AS  (E_W + WT)
#define SMEM_E ((E_AS + WT) * 4)        // 70272 B

#define ZERO_BLKS 12500

// device scratch
__device__ uint32_t g_q1b[(size_t)N_NODES * 64];
__device__ uint32_t g_q2b[(size_t)N_NODES * 64];
__device__ uint32_t g_kmb[(size_t)N_NODES * 64];
__device__ uint32_t g_aggb[(size_t)N_NODES * 64];   // bf16x2 accumulators
__device__ float g_deg[N_NODES];
__device__ float g_odeg[N_NODES];
__device__ float g_Mt[DIM * DIM];
__device__ float g_A1[DIM * DIM];
__device__ float g_A2[DIM * DIM];
__device__ float g_B[DIM * DIM];
__device__ float g_bc[DIM];
__device__ float g_v[DIM];
__device__ float g_c[1];
__device__ float g_bq1[DIM];
__device__ float g_u[DIM];

// ---------------------------------------------------------------------------
__device__ __forceinline__ float tanha(float x) {
    float y;
    asm("tanh.approx.f32 %0, %1;" : "=f"(y) : "f"(x));
    return y;
}
__device__ __forceinline__ uint32_t packbf(float lo, float hi) {
    uint32_t r;
    asm("cvt.rn.bf16x2.f32 %0, %1, %2;" : "=r"(r) : "f"(hi), "f"(lo));
    return r;
}
__device__ __forceinline__ float bflo(uint32_t u) {
    return __uint_as_float(u << 16);
}
__device__ __forceinline__ float bfhi(uint32_t u) {
    return __uint_as_float(u & 0xffff0000u);
}
__device__ __forceinline__ void mma_bf16(float* c4, uint32_t a0, uint32_t a1,
                                         uint32_t a2, uint32_t a3,
                                         uint32_t b0, uint32_t b1) {
    asm volatile(
        "mma.sync.aligned.m16n8k16.row.col.f32.bf16.bf16.f32 "
        "{%0,%1,%2,%3},{%4,%5,%6,%7},{%8,%9},{%0,%1,%2,%3};"
        : "+f"(c4[0]), "+f"(c4[1]), "+f"(c4[2]), "+f"(c4[3])
        : "r"(a0), "r"(a1), "r"(a2), "r"(a3), "r"(b0), "r"(b1));
}
__device__ __forceinline__ void red_bf16x8(uint32_t* ptr, uint32_t a,
                                           uint32_t b, uint32_t c, uint32_t d) {
    asm volatile(
        "red.global.add.noftz.v4.bf16x2 [%0], {%1, %2, %3, %4};"
        :: "l"(ptr), "r"(a), "r"(b), "r"(c), "r"(d) : "memory");
}

#define ZERO_ACC(acc)                                   \
    _Pragma("unroll") for (int _m = 0; _m < 2; _m++)    \
    _Pragma("unroll") for (int _n = 0; _n < 4; _n++)    \
    _Pragma("unroll") for (int _j = 0; _j < 4; _j++) acc[_m][_n][_j] = 0.f;

// bf16 inner GEMM (proven): warp tile 32x32, 8 kk steps of K=16
__device__ __forceinline__ void gemm_bf(const uint32_t* As, const uint32_t* Wb,
                                        float acc[2][4][4], int R0, int C0,
                                        int gr, int tg) {
#pragma unroll
    for (int kk = 0; kk < 8; kk++) {
        uint32_t a[2][4];
#pragma unroll
        for (int mt = 0; mt < 2; mt++) {
            const uint32_t* p = As + (R0 + mt * 16 + gr) * E_STRIDE + kk * 8 + tg;
            a[mt][0] = p[0];
            a[mt][1] = p[8 * E_STRIDE];
            a[mt][2] = p[4];
            a[mt][3] = p[8 * E_STRIDE + 4];
        }
#pragma unroll
        for (int nt = 0; nt < 4; nt++) {
            const uint32_t* q = Wb + (C0 + nt * 8 + gr) * E_STRIDE + kk * 8 + tg;
            uint32_t b0 = q[0];
            uint32_t b1 = q[4];
#pragma unroll
            for (int mt = 0; mt < 2; mt++)
                mma_bf16(acc[mt][nt], a[mt][0], a[mt][1], a[mt][2], a[mt][3],
                         b0, b1);
        }
    }
}

// W loader (fp32 row-major [n][k] -> bf16 packed)
__device__ __forceinline__ void load_W_bf(uint32_t* Wb,
                                          const float* __restrict__ W, int tid) {
#pragma unroll
    for (int i = 0; i < 8; i++) {
        int idx = i * 512 + tid;
        int n = idx >> 5, q = idx & 31;
        float4 w = *(const float4*)(W + n * DIM + q * 4);
        Wb[n * E_STRIDE + q * 2 + 0] = packbf(w.x, w.y);
        Wb[n * E_STRIDE + q * 2 + 1] = packbf(w.z, w.w);
    }
}

// A loader: fp32 source -> bf16 tile
__device__ __forceinline__ void load_A_f32(uint32_t* As,
                                           const float* __restrict__ A,
                                           int row0, int M, int tid) {
#pragma unroll
    for (int i = 0; i < 8; i++) {
        int idx = i * 512 + tid;
        int r = idx >> 5, q = idx & 31;
        int row = row0 + r;
        float4 v = make_float4(0.f, 0.f, 0.f, 0.f);
        if (row < M) v = *(const float4*)(A + (size_t)row * DIM + q * 4);
        As[r * E_STRIDE + q * 2 + 0] = packbf(v.x, v.y);
        As[r * E_STRIDE + q * 2 + 1] = packbf(v.z, v.w);
    }
}

// A loader: bf16 source -> bf16 tile (verbatim)
__device__ __forceinline__ void load_A_b16(uint32_t* As,
                                           const uint32_t* __restrict__ A,
                                           int row0, int M, int tid) {
#pragma unroll
    for (int i = 0; i < 4; i++) {
        int idx = i * 512 + tid;
        int r = idx >> 4, h = idx & 15;
        int row = row0 + r;
        uint4 v = make_uint4(0, 0, 0, 0);
        if (row < M) v = *(const uint4*)(A + (size_t)row * 64 + h * 4);
        *(uint4*)(As + r * E_STRIDE + h * 4) = v;
    }
}

// ---------------------------------------------------------------------------
// NODE mega-kernel: 5 GEMMs per 128-row block, t/h2 resident in smem.
__global__ void __launch_bounds__(512, 1)
k_node(const float* __restrict__ x, const uint32_t* __restrict__ aggb,
       const float* __restrict__ A1, const float* __restrict__ bq1,
       const float* __restrict__ A2, const float* __restrict__ B,
       const float* __restrict__ uu, const float* __restrict__ K0b,
       const float* __restrict__ deg, const float* __restrict__ K1W,
       const float* __restrict__ K1b, const float* __restrict__ Mt,
       const float* __restrict__ bc, const float* __restrict__ vv,
       const float* __restrict__ cc, const float* __restrict__ odeg,
       uint32_t* __restrict__ q1b, uint32_t* __restrict__ q2b,
       uint32_t* __restrict__ kmb, float* __restrict__ out, int M) {
    extern __shared__ uint32_t smu[];
    float* BQ1 = (float*)(smu + M_BQ1);
    float* BK0 = (float*)(smu + M_K0B);
    float* BU  = (float*)(smu + M_U);
    float* BK1 = (float*)(smu + M_K1B);
    float* BBC = (float*)(smu + M_BC);
    float* V   = (float*)(smu + M_V);
    float* RED = (float*)(smu + M_RED);
    uint32_t* WA1 = smu + M_W0;
    uint32_t* WA2 = smu + M_W0 + WT;
    uint32_t* WB  = smu + M_W0 + 2 * WT;
    uint32_t* WK1 = smu + M_W0 + 3 * WT;
    uint32_t* WMT = smu + M_W0 + 4 * WT;
    uint32_t* As  = smu + M_AS;
    const int tid = threadIdx.x;
    if (tid < 128) { BQ1[tid] = __ldg(bq1 + tid); BK0[tid] = __ldg(K0b + tid);
                     BU[tid] = __ldg(uu + tid); BK1[tid] = __ldg(K1b + tid);
                     BBC[tid] = __ldg(bc + tid); V[tid] = __ldg(vv + tid); }
    const float cval = __ldg(cc);
    load_W_bf(WA1, A1, tid);
    load_W_bf(WA2, A2, tid);
    load_W_bf(WB, B, tid);
    load_W_bf(WK1, K1W, tid);
    load_W_bf(WMT, Mt, tid);
    __syncthreads();

    const int wid = tid >> 5, lane = tid & 31;
    const int gr = lane >> 2, tg = lane & 3;
    const int R0 = (wid >> 2) * 32, C0 = (wid & 3) * 32;
    const int tiles = (M + 127) >> 7;
    float part = 0.f;

    for (int tile = blockIdx.x; tile < tiles; tile += gridDim.x) {
        const int row0 = tile << 7;
        float acc[2][4][4];

        // ---- phase 1: q1/q2 from x tile ----
        __syncthreads();
        load_A_f32(As, x, row0, M, tid);
        __syncthreads();
#pragma unroll
        for (int pass = 0; pass < 2; pass++) {
            const uint32_t* Ws = pass ? WA2 : WA1;
            uint32_t* C = pass ? q2b : q1b;
            ZERO_ACC(acc);
            gemm_bf(As, Ws, acc, R0, C0, gr, tg);
#pragma unroll
            for (int mt = 0; mt < 2; mt++) {
                int rl0 = R0 + mt * 16 + gr, rl1 = rl0 + 8;
#pragma unroll
                for (int nt = 0; nt < 4; nt++) {
                    int c0 = C0 + nt * 8 + 2 * tg;
                    float b0 = pass ? 0.f : BQ1[c0];
                    float b1 = pass ? 0.f : BQ1[c0 + 1];
                    if (row0 + rl0 < M)
                        C[(size_t)(row0 + rl0) * 64 + (c0 >> 1)] =
                            packbf(acc[mt][nt][0] + b0, acc[mt][nt][1] + b1);
                    if (row0 + rl1 < M)
                        C[(size_t)(row0 + rl1) * 64 + (c0 >> 1)] =
                            packbf(acc[mt][nt][2] + b0, acc[mt][nt][3] + b1);
                }
            }
        }

        // ---- phase 2: t = tanh(aggb@B^T + deg*u + K0b) (t stays in smem) ----
        __syncthreads();
        load_A_b16(As, aggb, row0, M, tid);
        __syncthreads();
        ZERO_ACC(acc);
        gemm_bf(As, WB, acc, R0, C0, gr, tg);
        __syncthreads();
#pragma unroll
        for (int mt = 0; mt < 2; mt++) {
            int rl0 = R0 + mt * 16 + gr, rl1 = rl0 + 8;
            int g0 = row0 + rl0, g1 = row0 + rl1;
            float d0 = (g0 < M) ? __ldg(deg + g0) : 0.f;
            float d1 = (g1 < M) ? __ldg(deg + g1) : 0.f;
#pragma unroll
            for (int nt = 0; nt < 4; nt++) {
                int c0 = C0 + nt * 8 + 2 * tg;
                float b0 = BK0[c0], b1 = BK0[c0 + 1];
                float u0 = BU[c0], u1 = BU[c0 + 1];
                As[rl0 * E_STRIDE + (c0 >> 1)] = packbf(
                    tanha(fmaf(d0, u0, acc[mt][nt][0] + b0)),
                    tanha(fmaf(d0, u1, acc[mt][nt][1] + b1)));
                As[rl1 * E_STRIDE + (c0 >> 1)] = packbf(
                    tanha(fmaf(d1, u0, acc[mt][nt][2] + b0)),
                    tanha(fmaf(d1, u1, acc[mt][nt][3] + b1)));
            }
        }
        __syncthreads();

        // ---- phase 3: h2 = relu(t@K1^T + K1b) (in place) ----
        ZERO_ACC(acc);
        gemm_bf(As, WK1, acc, R0, C0, gr, tg);
        __syncthreads();
#pragma unroll
        for (int mt = 0; mt < 2; mt++) {
            int rl0 = R0 + mt * 16 + gr, rl1 = rl0 + 8;
#pragma unroll
            for (int nt = 0; nt < 4; nt++) {
                int c0 = C0 + nt * 8 + 2 * tg;
                float b0 = BK1[c0], b1 = BK1[c0 + 1];
                As[rl0 * E_STRIDE + (c0 >> 1)] =
                    packbf(fmaxf(acc[mt][nt][0] + b0, 0.f),
                           fmaxf(acc[mt][nt][1] + b1, 0.f));
                As[rl1 * E_STRIDE + (c0 >> 1)] =
                    packbf(fmaxf(acc[mt][nt][2] + b0, 0.f),
                           fmaxf(acc[mt][nt][3] + b1, 0.f));
            }
        }
        __syncthreads();

        // ---- phase 4: kb fold + km = h2@M + bc ----
        {
            int r = tid >> 2, qt = tid & 3;
            const uint32_t* hp = As + r * E_STRIDE + qt * 16;
            float s = 0.f;
#pragma unroll
            for (int j = 0; j < 16; j++) {
                uint32_t w = hp[j];
                s = fmaf(bflo(w), V[qt * 32 + 2 * j], s);
                s = fmaf(bfhi(w), V[qt * 32 + 2 * j + 1], s);
            }
            s += __shfl_xor_sync(0xffffffffu, s, 1);
            s += __shfl_xor_sync(0xffffffffu, s, 2);
            if (qt == 0 && row0 + r < M)
                part = fmaf(s + cval, __ldg(odeg + row0 + r), part);
        }
        ZERO_ACC(acc);
        gemm_bf(As, WMT, acc, R0, C0, gr, tg);
#pragma unroll
        for (int mt = 0; mt < 2; mt++) {
            int rl0 = R0 + mt * 16 + gr, rl1 = rl0 + 8;
#pragma unroll
            for (int nt = 0; nt < 4; nt++) {
                int c0 = C0 + nt * 8 + 2 * tg;
                float b0 = BBC[c0], b1 = BBC[c0 + 1];
                if (row0 + rl0 < M)
                    kmb[(size_t)(row0 + rl0) * 64 + (c0 >> 1)] =
                        packbf(acc[mt][nt][0] + b0, acc[mt][nt][1] + b1);
                if (row0 + rl1 < M)
                    kmb[(size_t)(row0 + rl1) * 64 + (c0 >> 1)] =
                        packbf(acc[mt][nt][2] + b0, acc[mt][nt][3] + b1);
            }
        }
    }
#pragma unroll
    for (int o = 16; o > 0; o >>= 1)
        part += __shfl_xor_sync(0xffffffffu, part, o);
    __syncthreads();
    if (lane == 0) RED[wid] = part;
    __syncthreads();
    if (tid == 0) {
        float s = 0.f;
#pragma unroll
        for (int w = 0; w < 16; w++) s += RED[w];
        atomicAdd(out, s);
    }
}

// ---------------------------------------------------------------------------
// EDGE (bf16, proven): out += sum_e relu(tanh(q1[s]+q2[d])@U1^T + b1).km[s]
__global__ void __launch_bounds__(512, 1)
k_edge(const int* __restrict__ src, const int* __restrict__ dst,
       const uint32_t* __restrict__ Q1b, const uint32_t* __restrict__ Q2b,
       const float* __restrict__ U1W, const float* __restrict__ U1b,
       const uint32_t* __restrict__ kmb, float* __restrict__ out, int M) {
    extern __shared__ uint32_t smu[];
    float* B2 = (float*)(smu + E_B2);
    float* RED = (float*)(smu + E_RED);
    uint32_t* Wb = smu + E_W;
    uint32_t* As = smu + E_AS;
    const int tid = threadIdx.x;
    if (tid < 128) B2[tid] = __ldg(U1b + tid);
    load_W_bf(Wb, U1W, tid);
    __syncthreads();

    const int wid = tid >> 5, lane = tid & 31;
    const int gr = lane >> 2, tg = lane & 3;
    const int R0 = (wid >> 2) * 32, C0 = (wid & 3) * 32;
    const int tiles = (M + 127) >> 7;
    float part = 0.f;

    for (int tile = blockIdx.x; tile < tiles; tile += gridDim.x) {
        const int row0 = tile << 7;
        __syncthreads();
#pragma unroll
        for (int i = 0; i < 4; i++) {
            int idx = i * 512 + tid;
            int r = idx >> 4, h = idx & 15;
            int row = row0 + r;
            uint4 va = make_uint4(0, 0, 0, 0), vb = va;
            if (row < M) {
                int s = __ldg(src + row);
                int d = __ldg(dst + row);
                va = *(const uint4*)(Q1b + (size_t)s * 64 + h * 4);
                vb = *(const uint4*)(Q2b + (size_t)d * 64 + h * 4);
            }
            uint32_t o[4];
            uint32_t av[4] = {va.x, va.y, va.z, va.w};
            uint32_t bv[4] = {vb.x, vb.y, vb.z, vb.w};
#pragma unroll
            for (int j = 0; j < 4; j++) {
                float lo = tanha(bflo(av[j]) + bflo(bv[j]));
                float hi = tanha(bfhi(av[j]) + bfhi(bv[j]));
                o[j] = packbf(lo, hi);
            }
            *(uint4*)(As + r * E_STRIDE + h * 4) =
                make_uint4(o[0], o[1], o[2], o[3]);
        }
        __syncthreads();
        const uint32_t* kmp[4];
        bool kv[4];
#pragma unroll
        for (int j = 0; j < 4; j++) {
            int rg = row0 + R0 + ((j >> 1) * 16) + ((j & 1) * 8) + gr;
            kv[j] = rg < M;
            int s = kv[j] ? __ldg(src + rg) : 0;
            kmp[j] = kmb + (size_t)s * 64;
        }
        float acc[2][4][4];
        ZERO_ACC(acc);
        gemm_bf(As, Wb, acc, R0, C0, gr, tg);
#pragma unroll
        for (int mt = 0; mt < 2; mt++) {
            const uint32_t* km0 = kmp[mt * 2];
            const uint32_t* km1 = kmp[mt * 2 + 1];
            bool v0 = kv[mt * 2], v1 = kv[mt * 2 + 1];
#pragma unroll
            for (int nt = 0; nt < 4; nt++) {
                int c0 = C0 + nt * 8 + 2 * tg;
                float b0 = B2[c0], b1 = B2[c0 + 1];
                uint32_t kw0 = v0 ? km0[c0 >> 1] : 0u;
                uint32_t kw1 = v1 ? km1[c0 >> 1] : 0u;
                part = fmaf(fmaxf(acc[mt][nt][0] + b0, 0.f), bflo(kw0), part);
                part = fmaf(fmaxf(acc[mt][nt][1] + b1, 0.f), bfhi(kw0), part);
                part = fmaf(fmaxf(acc[mt][nt][2] + b0, 0.f), bflo(kw1), part);
                part = fmaf(fmaxf(acc[mt][nt][3] + b1, 0.f), bfhi(kw1), part);
            }
        }
    }
#pragma unroll
    for (int o = 16; o > 0; o >>= 1)
        part += __shfl_xor_sync(0xffffffffu, part, o);
    __syncthreads();
    if (lane == 0) RED[wid] = part;
    __syncthreads();
    if (tid == 0) {
        float s = 0.f;
#pragma unroll
        for (int w = 0; w < 16; w++) s += RED[w];
        atomicAdd(out, s);
    }
}

// ---------------------------------------------------------------------------
// scatter: aggb[dst[e]] += bf16(x[src[e]]) via v4.bf16x2 reds; 16 thr/edge
__global__ void scatter_kernel(const float* __restrict__ x,
                               const int* __restrict__ src,
                               const int* __restrict__ dst) {
    int idx = blockIdx.x * blockDim.x + threadIdx.x;
    int e = idx >> 4;
    int h = idx & 15;            // 8 floats per thread
    if (e < N_EDGES) {
        int s = __ldg(src + e);
        int d = __ldg(dst + e);
        const float* xp = x + (size_t)s * DIM + h * 8;
        float4 v0 = *(const float4*)(xp);
        float4 v1 = *(const float4*)(xp + 4);
        red_bf16x8(g_aggb + (size_t)d * 64 + h * 4,
                   packbf(v0.x, v0.y), packbf(v0.z, v0.w),
                   packbf(v1.x, v1.y), packbf(v1.z, v1.w));
        if (h == 0) {
            atomicAdd(g_deg + d, 1.0f);
            atomicAdd(g_odeg + s, 1.0f);
        }
    }
}

// ---------------------------------------------------------------------------
// FUSED zero + prep (role by blockIdx); g_Mt stored TRANSPOSED
__global__ void k_zero_prep(float* __restrict__ out,
                            const float* __restrict__ K2W,
                            const float* __restrict__ K2b,
                            const float* __restrict__ U2W,
                            const float* __restrict__ U2b,
                            const float* __restrict__ U0W,
                            const float* __restrict__ U0b,
                            const float* __restrict__ WencP1,
                            const float* __restrict__ bencP1,
                            const float* __restrict__ WencP2,
                            const float* __restrict__ bencP2,
                            const float* __restrict__ K0W,
                            const float* __restrict__ WencK,
                            const float* __restrict__ bencK) {
    __shared__ float sa[128];
    const int tid = threadIdx.x;
    if (blockIdx.x < ZERO_BLKS) {
        int i = blockIdx.x * 256 + tid;
        if (i < N_NODES * 64) g_aggb[i] = 0u;
        if (i < N_NODES) { g_deg[i] = 0.0f; g_odeg[i] = 0.0f; }
        if (i == 0) out[0] = 0.0f;
        return;
    }
    const int b = blockIdx.x - ZERO_BLKS;
    const int t = tid;
    const bool a = t < 128;
    if (b < 128) {              // M[b][t] -> g_Mt[t][b] (transposed)
        if (a) sa[t] = K2W[t * DIM + b];
        __syncthreads();
        if (a) {
            float s = 0.f;
            for (int k = 0; k < 128; k++) s = fmaf(sa[k], U2W[k * DIM + t], s);
            g_Mt[t * DIM + b] = s;
        }
    } else if (b < 256) {
        int r = b - 128;
        if (a) sa[t] = U0W[r * DIM + t];
        __syncthreads();
        if (a) {
            float s = 0.f;
            for (int k = 0; k < 128; k++) s = fmaf(sa[k], WencP1[k * DIM + t], s);
            g_A1[r * DIM + t] = s;
        }
    } else if (b < 384) {
        int r = b - 256;
        if (a) sa[t] = U0W[r * DIM + t];
        __syncthreads();
        if (a) {
            float s = 0.f;
            for (int k = 0; k < 128; k++) s = fmaf(sa[k], WencP2[k * DIM + t], s);
            g_A2[r * DIM + t] = s;
        }
    } else if (b < 512) {
        int r = b - 384;
        if (a) sa[t] = K0W[r * DIM + t];
        __syncthreads();
        if (a) {
            float s = 0.f;
            for (int k = 0; k < 128; k++) s = fmaf(sa[k], WencK[k * DIM + t], s);
            g_B[r * DIM + t] = s;
        }
    } else if (b == 512) {
        if (a) sa[t] = K2b[t];
        __syncthreads();
        if (a) {
            float s = 0.f;
            for (int k = 0; k < 128; k++) s = fmaf(sa[k], U2W[k * DIM + t], s);
            g_bc[t] = s;
        }
    } else if (b == 513) {
        if (a) {
            float s = 0.f;
            for (int k = 0; k < 128; k++) s = fmaf(K2W[k * DIM + t], U2b[k], s);
            g_v[t] = s;
            if (t == 0) {
                float cv = 0.f;
                for (int k = 0; k < 128; k++) cv = fmaf(K2b[k], U2b[k], cv);
                g_c[0] = cv;
            }
        }
    } else if (b == 514) {
        if (a) sa[t] = __ldg(bencP1 + t) + __ldg(bencP2 + t);
        __syncthreads();
        if (a) {
            float s = 0.f;
            for (int k = 0; k < 128; k++) s = fmaf(U0W[t * DIM + k], sa[k], s);
            g_bq1[t] = s + __ldg(U0b + t);
        }
    } else {
        if (a) {
            float s = 0.f;
            for (int k = 0; k < 128; k++)
                s = fmaf(K0W[t * DIM + k], __ldg(bencK + k), s);
            g_u[t] = s;
        }
    }
}

// ---------------------------------------------------------------------------
extern "C" void kernel_launch(void* const* d_in, const int* in_sizes, int n_in,
                              void* d_out, int out_size) {
    const float* x      = (const float*)d_in[0];
    const int*   src    = (const int*)d_in[1];
    const int*   dst    = (const int*)d_in[2];
    const float* WencK  = (const float*)d_in[3];
    const float* bencK  = (const float*)d_in[4];
    const float* WencP1 = (const float*)d_in[5];
    const float* bencP1 = (const float*)d_in[6];
    const float* WencP2 = (const float*)d_in[7];
    const float* bencP2 = (const float*)d_in[8];
    const float* K0W = (const float*)d_in[9];
    const float* K0b = (const float*)d_in[10];
    const float* K1W = (const float*)d_in[11];
    const float* K1b = (const float*)d_in[12];
    const float* K2W = (const float*)d_in[13];
    const float* K2b = (const float*)d_in[14];
    const float* U0W = (const float*)d_in[15];
    const float* U0b = (const float*)d_in[16];
    const float* U1W = (const float*)d_in[17];
    const float* U1b = (const float*)d_in[18];
    const float* U2W = (const float*)d_in[19];
    const float* U2b = (const float*)d_in[20];
    float* out = (float*)d_out;

    float *deg, *odeg, *Mt, *A1, *A2, *Bw, *bc, *vv, *cc, *bq1, *uu;
    uint32_t *q1b, *q2b, *kmb, *aggb;
    cudaGetSymbolAddress((void**)&q1b, g_q1b);
    cudaGetSymbolAddress((void**)&q2b, g_q2b);
    cudaGetSymbolAddress((void**)&kmb, g_kmb);
    cudaGetSymbolAddress((void**)&aggb, g_aggb);
    cudaGetSymbolAddress((void**)&deg, g_deg);
    cudaGetSymbolAddress((void**)&odeg, g_odeg);
    cudaGetSymbolAddress((void**)&Mt, g_Mt);
    cudaGetSymbolAddress((void**)&A1, g_A1);
    cudaGetSymbolAddress((void**)&A2, g_A2);
    cudaGetSymbolAddress((void**)&Bw, g_B);
    cudaGetSymbolAddress((void**)&bc, g_bc);
    cudaGetSymbolAddress((void**)&vv, g_v);
    cudaGetSymbolAddress((void**)&cc, g_c);
    cudaGetSymbolAddress((void**)&bq1, g_bq1);
    cudaGetSymbolAddress((void**)&uu, g_u);

    cudaFuncSetAttribute(k_node, cudaFuncAttributeMaxDynamicSharedMemorySize, SMEM_M);
    cudaFuncSetAttribute(k_edge, cudaFuncAttributeMaxDynamicSharedMemorySize, SMEM_E);

    k_zero_prep<<<ZERO_BLKS + 516, 256>>>(out, K2W, K2b, U2W, U2b, U0W, U0b,
                                          WencP1, bencP1, WencP2, bencP2,
                                          K0W, WencK, bencK);

    scatter_kernel<<<(N_EDGES * 16 + 255) / 256, 256>>>(x, src, dst);

    k_node<<<GRID_P, 512, SMEM_M>>>(x, aggb, A1, bq1, A2, Bw, uu, K0b, deg,
                                    K1W, K1b, Mt, bc, vv, cc, odeg,
                                    q1b, q2b, kmb, out, N_NODES);

    k_edge<<<GRID_P, 512, SMEM_E>>>(src, dst, q1b, q2b, U1W, U1b, kmb, out,
                                    N_EDGES);
}